// round 8
// baseline (speedup 1.0000x reference)
#include <cuda_runtime.h>
#include <cstdint>
#include <cstddef>

// Depthwise conv1d: B=8, L=16384, C=512, K=31, SAME, fp32.
// R5 architecture with RCH=128: cp.async -> warp-private SMEM slab ring
// (3 deep) + f32x2 32-slot ring-accumulator stencil, warp-local sync only.
// Stream step s = 0..158, input q = l0-16+s; input q adds w[k] to slot
// (s-1-k)&31; output l0+s-31 stored from slot (s+1)&31 at end of step s.

constexpr int B_   = 8;
constexpr int L_   = 16384;
constexpr int C_   = 512;
constexpr int K_   = 31;
constexpr int RCH  = 128;          // L outputs per block
constexpr int TPB  = 128;          // 4 warps; warp owns 32 channel pairs
constexpr int CW   = C_ / 2;       // 256 u64 per L-row
constexpr int SLAB = 16;           // L-rows per smem slab
constexpr int ROWB = 2048;         // bytes per L-row (512 floats)
constexpr int NSLAB = 10;          // 160 stream rows (need 159)

using u64 = unsigned long long;

__device__ __forceinline__ u64 ffma2(u64 a, u64 b, u64 c) {
    u64 d;
    asm("fma.rn.f32x2 %0, %1, %2, %3;" : "=l"(d) : "l"(a), "l"(b), "l"(c));
    return d;
}
__device__ __forceinline__ void stg_cs(u64* p, u64 v) {
    asm volatile("st.global.cs.b64 [%0], %1;" :: "l"(p), "l"(v));
}
__device__ __forceinline__ void cpa16(unsigned saddr, const void* gptr, unsigned sz) {
    asm volatile("cp.async.cg.shared.global [%0], [%1], 16, %2;\n"
                 :: "r"(saddr), "l"(gptr), "r"(sz));
}
__device__ __forceinline__ void cpcommit() { asm volatile("cp.async.commit_group;\n"); }
template <int N>
__device__ __forceinline__ void cpwait() { asm volatile("cp.async.wait_group %0;\n" :: "n"(N)); }

template <bool GUARD>
struct Copier {
    const char* xw;     // x base for (batch, warp's first channel pair)
    unsigned    sbase;  // shared addr of this warp's buffer[0] (+lane offsets)
    int         rl;     // lane>>4  (row parity this lane serves)
    int         o16;    // (lane&15)*16 (byte offset within 256B row)
    int         q0;     // l0 - 16

    // Copy one slab (16 rows x 256B for this warp) into buffer buf.
    // OOB rows (SAME padding) zero-filled via src_size = 0.
    __device__ __forceinline__ void issue(int slab, int buf) const {
        if (slab >= NSLAB) { cpcommit(); return; }   // uniform group count
        unsigned dst = sbase + (unsigned)buf * (SLAB * 256)
                     + (unsigned)(rl * 256 + o16);
        const int qb = q0 + slab * SLAB + rl;
        if (GUARD) {
#pragma unroll
            for (int j = 0; j < 8; ++j) {
                int q = qb + 2 * j;
                int qc = q < 0 ? 0 : (q >= L_ ? L_ - 1 : q);
                unsigned sz = (q >= 0 && q < L_) ? 16u : 0u;
                cpa16(dst + (unsigned)(j * 512), xw + (long)qc * ROWB + o16, sz);
            }
        } else {
            const char* g = xw + (long)qb * ROWB + o16;
#pragma unroll
            for (int j = 0; j < 8; ++j)
                cpa16(dst + (unsigned)(j * 512), g + (long)j * (2 * ROWB), 16u);
        }
        cpcommit();
    }
};

// One 16-row slab at ring phase PHASE (0 or 16). LAST: stop at u=14.
template <int PHASE, bool LAST>
__device__ __forceinline__ void do_slab(const u64* __restrict__ sl, int lane,
                                        const u64* __restrict__ wr,
                                        u64* __restrict__ acc, u64 bb,
                                        u64*& op)
{
#pragma unroll
    for (int u = 0; u < (LAST ? 15 : 16); ++u) {
        u64 v = sl[u * 32 + lane];
#pragma unroll
        for (int k = 0; k < K_; ++k) {
            const int t = (PHASE + u - 1 - k) & 31;
            acc[t] = ffma2(v, wr[k], acc[t]);
        }
        const int st = (PHASE + u + 1) & 31;
        stg_cs(op, acc[st]); acc[st] = bb; op += CW;
    }
}

template <bool GUARD>
__device__ __forceinline__ void conv_body(const float* __restrict__ x,
                                          const float* __restrict__ w,
                                          const float* __restrict__ bias,
                                          float* __restrict__ out,
                                          u64 (*sbuf)[3][SLAB][32])
{
    const int lane = threadIdx.x & 31;
    const int warp = threadIdx.x >> 5;
    const int cp   = blockIdx.y * TPB + threadIdx.x;     // channel pair
    const int cp0w = blockIdx.y * TPB + warp * 32;
    const int b    = blockIdx.z;
    const int l0   = blockIdx.x * RCH;

    Copier<GUARD> cc;
    cc.xw    = (const char*)x + (size_t)b * ((size_t)L_ * C_ * 4) + (size_t)cp0w * 8;
    cc.sbase = (unsigned)__cvta_generic_to_shared(&sbuf[warp][0][0][0]);
    cc.rl    = lane >> 4;
    cc.o16   = (lane & 15) * 16;
    cc.q0    = l0 - 16;

    const u64* wg = (const u64*)w;
    u64 wr[K_];
#pragma unroll
    for (int k = 0; k < K_; ++k) wr[k] = wg[k * CW + cp];
    const u64 bb = ((const u64*)bias)[cp];

    u64 acc[32];
#pragma unroll
    for (int i = 0; i < 32; ++i) acc[i] = bb;

    u64* op = (u64*)out + (size_t)b * ((size_t)L_ * CW) + (size_t)l0 * CW + cp;

    cc.issue(0, 0); cc.issue(1, 1); cc.issue(2, 2);
    const u64* sw = &sbuf[warp][0][0][0];

    // ---- slab 0 (s = 0..15): ramp, contributions k <= s-1, no stores ----
    cpwait<2>(); __syncwarp();
#pragma unroll
    for (int u = 1; u < 16; ++u) {
        u64 v = sw[u * 32 + lane];
#pragma unroll
        for (int k = 0; k < u; ++k) {
            const int t = u - 1 - k;
            acc[t] = ffma2(v, wr[k], acc[t]);
        }
    }
    __syncwarp(); cc.issue(3, 0);

    // ---- slab 1 (s = 16..31): ramp, k <= 15+u; first store at s=31 ----
    cpwait<2>(); __syncwarp();
#pragma unroll
    for (int u = 0; u < 16; ++u) {
        u64 v = sw[(SLAB * 32) + u * 32 + lane];
#pragma unroll
        for (int k = 0; k <= 15 + u; ++k) {
            const int t = 15 + u - k;
            acc[t] = ffma2(v, wr[k], acc[t]);
        }
        if (u == 15) { stg_cs(op, acc[0]); acc[0] = bb; op += CW; }
    }
    __syncwarp(); cc.issue(4, 1);

    // ---- main slabs 2..9 (full stencil); slab n: phase 16*(n&1), buf n%3 ----
    cpwait<2>(); __syncwarp();
    do_slab<0,  false>(sw + 2 * (SLAB * 32), lane, wr, acc, bb, op);
    __syncwarp(); cc.issue(5, 2);

    cpwait<2>(); __syncwarp();
    do_slab<16, false>(sw + 0 * (SLAB * 32), lane, wr, acc, bb, op);
    __syncwarp(); cc.issue(6, 0);

    cpwait<2>(); __syncwarp();
    do_slab<0,  false>(sw + 1 * (SLAB * 32), lane, wr, acc, bb, op);
    __syncwarp(); cc.issue(7, 1);

    cpwait<2>(); __syncwarp();
    do_slab<16, false>(sw + 2 * (SLAB * 32), lane, wr, acc, bb, op);
    __syncwarp(); cc.issue(8, 2);

    cpwait<2>(); __syncwarp();
    do_slab<0,  false>(sw + 0 * (SLAB * 32), lane, wr, acc, bb, op);
    __syncwarp(); cc.issue(9, 0);

    cpwait<2>(); __syncwarp();
    do_slab<16, false>(sw + 1 * (SLAB * 32), lane, wr, acc, bb, op);
    __syncwarp(); cc.issue(10, 1);    // dummy

    cpwait<2>(); __syncwarp();
    do_slab<0,  false>(sw + 2 * (SLAB * 32), lane, wr, acc, bb, op);
    __syncwarp(); cc.issue(11, 2);    // dummy

    cpwait<2>(); __syncwarp();
    do_slab<16, true >(sw + 0 * (SLAB * 32), lane, wr, acc, bb, op);
}

__global__ void __launch_bounds__(TPB, 3)
dwconv_kernel(const float* __restrict__ x, const float* __restrict__ w,
              const float* __restrict__ bias, float* __restrict__ out)
{
    __shared__ __align__(16) u64 sbuf[4][3][SLAB][32];   // 48 KB

    if (blockIdx.x == 0 || blockIdx.x == (L_ / RCH) - 1)
        conv_body<true>(x, w, bias, out, sbuf);
    else
        conv_body<false>(x, w, bias, out, sbuf);
}

extern "C" void kernel_launch(void* const* d_in, const int* in_sizes, int n_in,
                              void* d_out, int out_size)
{
    const float* x    = (const float*)d_in[0];   // [B, L, C]
    const float* w    = (const float*)d_in[1];   // [K, C, 1]
    const float* bias = (const float*)d_in[2];   // [C]
    float*       out  = (float*)d_out;           // [B, L, C]

    dim3 grid(L_ / RCH, (C_ / 2) / TPB, B_);     // (128, 2, 8) = 2048 CTAs
    dwconv_kernel<<<grid, TPB>>>(x, w, bias, out);
}

// round 9
// speedup vs baseline: 1.3822x; 1.3822x over previous
#include <cuda_runtime.h>
#include <cstdint>
#include <cstddef>

// Depthwise conv1d: B=8, L=16384, C=512, K=31, SAME, fp32.
// RCH=64, cp.async -> warp-private SMEM slab ring (4 deep x 12 rows, 48 KB)
// + f32x2 32-slot ring-accumulator stencil, warp-local sync only.
// Stream step s = 0..94, input q = l0-16+s; taps k <= min(30, s-1);
// input q adds w[k] to slot (s-1-k)&31; output l0+s-31 stored from slot
// (s+1)&31 at end of step s (s >= 31).

constexpr int B_   = 8;
constexpr int L_   = 16384;
constexpr int C_   = 512;
constexpr int K_   = 31;
constexpr int RCH  = 64;           // L outputs per block
constexpr int TPB  = 128;          // 4 warps; warp owns 32 channel pairs
constexpr int CW   = C_ / 2;       // 256 u64 per L-row
constexpr int SLAB = 12;           // L-rows per smem slab
constexpr int NBUF = 4;            // ring depth
constexpr int ROWB = 2048;         // bytes per full L-row (512 floats)
constexpr int NSLAB = 8;           // 96 stream rows (need 95)

using u64 = unsigned long long;

__device__ __forceinline__ u64 ffma2(u64 a, u64 b, u64 c) {
    u64 d;
    asm("fma.rn.f32x2 %0, %1, %2, %3;" : "=l"(d) : "l"(a), "l"(b), "l"(c));
    return d;
}
__device__ __forceinline__ void stg_cs(u64* p, u64 v) {
    asm volatile("st.global.cs.b64 [%0], %1;" :: "l"(p), "l"(v));
}
__device__ __forceinline__ void cpa16(unsigned saddr, const void* gptr, unsigned sz) {
    asm volatile("cp.async.cg.shared.global [%0], [%1], 16, %2;\n"
                 :: "r"(saddr), "l"(gptr), "r"(sz));
}
__device__ __forceinline__ void cpcommit() { asm volatile("cp.async.commit_group;\n"); }
template <int N>
__device__ __forceinline__ void cpwait() { asm volatile("cp.async.wait_group %0;\n" :: "n"(N)); }

template <bool GUARD>
struct Copier {
    const char* xw;     // x base for (batch, warp's first channel pair)
    unsigned    sbase;  // warp's buffer[0] smem addr
    int         rl;     // lane>>4 (row parity this lane serves)
    int         o16;    // (lane&15)*16 (byte offset within 256B row)
    int         q0;     // l0 - 16

    // Copy one 12-row slab (3 KB for this warp) into buffer buf.
    // OOB rows (SAME padding) zero-filled via src_size = 0.
    __device__ __forceinline__ void issue(int slab, int buf) const {
        if (slab >= NSLAB) { cpcommit(); return; }   // uniform group count
        unsigned dst = sbase + (unsigned)buf * (SLAB * 256)
                     + (unsigned)(rl * 256 + o16);
        const int qb = q0 + slab * SLAB + rl;
        if (GUARD) {
#pragma unroll
            for (int j = 0; j < 6; ++j) {
                int q = qb + 2 * j;
                int qc = q < 0 ? 0 : (q >= L_ ? L_ - 1 : q);
                unsigned sz = (q >= 0 && q < L_) ? 16u : 0u;
                cpa16(dst + (unsigned)(j * 512), xw + (long)qc * ROWB + o16, sz);
            }
        } else {
            const char* g = xw + (long)qb * ROWB + o16;
#pragma unroll
            for (int j = 0; j < 6; ++j)
                cpa16(dst + (unsigned)(j * 512), g + (long)j * (2 * ROWB), 16u);
        }
        cpcommit();
    }
};

// One 12-row slab; absolute stream-step base SB (compile-time).
// Ramp clipping, slot math, and store predicate all fold at compile time.
template <int SB, bool LAST>
__device__ __forceinline__ void do_slab(const u64* __restrict__ sl, int lane,
                                        const u64* __restrict__ wr,
                                        u64* __restrict__ acc, u64 bb,
                                        u64*& op)
{
#pragma unroll
    for (int u = 0; u < (LAST ? 11 : 12); ++u) {
        const int s = SB + u;
        const u64 v = sl[u * 32 + lane];
#pragma unroll
        for (int k = 0; k < K_; ++k) {
            if (k <= s - 1) {                        // ramp clip (compile-time)
                const int t = (s - 1 - k) & 31;
                acc[t] = ffma2(v, wr[k], acc[t]);
            }
        }
        if (s >= 31) {                               // output o = l0 + s - 31
            const int st = (s + 1) & 31;
            stg_cs(op, acc[st]); acc[st] = bb; op += CW;
        }
    }
}

template <bool GUARD>
__device__ __forceinline__ void conv_body(const float* __restrict__ x,
                                          const float* __restrict__ w,
                                          const float* __restrict__ bias,
                                          float* __restrict__ out,
                                          u64 (*sbuf)[NBUF][SLAB][32])
{
    const int lane = threadIdx.x & 31;
    const int warp = threadIdx.x >> 5;
    const int cp   = blockIdx.y * TPB + threadIdx.x;     // channel pair
    const int cp0w = blockIdx.y * TPB + warp * 32;
    const int b    = blockIdx.z;
    const int l0   = blockIdx.x * RCH;

    Copier<GUARD> cc;
    cc.xw    = (const char*)x + (size_t)b * ((size_t)L_ * C_ * 4) + (size_t)cp0w * 8;
    cc.sbase = (unsigned)__cvta_generic_to_shared(&sbuf[warp][0][0][0]);
    cc.rl    = lane >> 4;
    cc.o16   = (lane & 15) * 16;
    cc.q0    = l0 - 16;

    const u64* wg = (const u64*)w;
    u64 wr[K_];
#pragma unroll
    for (int k = 0; k < K_; ++k) wr[k] = wg[k * CW + cp];
    const u64 bb = ((const u64*)bias)[cp];

    u64 acc[32];
#pragma unroll
    for (int i = 0; i < 32; ++i) acc[i] = bb;

    u64* op = (u64*)out + (size_t)b * ((size_t)L_ * CW) + (size_t)l0 * CW + cp;

    // prefetch 4 slabs
    cc.issue(0, 0); cc.issue(1, 1); cc.issue(2, 2); cc.issue(3, 3);
    const u64* sw = &sbuf[warp][0][0][0];

    // slab n: steps s = 12n .. 12n+11; buf = n & 3; after compute issue n+4.
    cpwait<3>(); __syncwarp();
    do_slab<0,  false>(sw + 0 * (SLAB * 32), lane, wr, acc, bb, op);
    __syncwarp(); cc.issue(4, 0);

    cpwait<3>(); __syncwarp();
    do_slab<12, false>(sw + 1 * (SLAB * 32), lane, wr, acc, bb, op);
    __syncwarp(); cc.issue(5, 1);

    cpwait<3>(); __syncwarp();
    do_slab<24, false>(sw + 2 * (SLAB * 32), lane, wr, acc, bb, op);
    __syncwarp(); cc.issue(6, 2);

    cpwait<3>(); __syncwarp();
    do_slab<36, false>(sw + 3 * (SLAB * 32), lane, wr, acc, bb, op);
    __syncwarp(); cc.issue(7, 3);

    cpwait<3>(); __syncwarp();
    do_slab<48, false>(sw + 0 * (SLAB * 32), lane, wr, acc, bb, op);
    __syncwarp(); cc.issue(8, 0);      // dummy

    cpwait<3>(); __syncwarp();
    do_slab<60, false>(sw + 1 * (SLAB * 32), lane, wr, acc, bb, op);
    __syncwarp(); cc.issue(9, 1);      // dummy

    cpwait<3>(); __syncwarp();
    do_slab<72, false>(sw + 2 * (SLAB * 32), lane, wr, acc, bb, op);
    __syncwarp(); cc.issue(10, 2);     // dummy

    cpwait<3>(); __syncwarp();
    do_slab<84, true >(sw + 3 * (SLAB * 32), lane, wr, acc, bb, op);
}

__global__ void __launch_bounds__(TPB, 3)
dwconv_kernel(const float* __restrict__ x, const float* __restrict__ w,
              const float* __restrict__ bias, float* __restrict__ out)
{
    __shared__ __align__(16) u64 sbuf[4][NBUF][SLAB][32];   // 48 KB

    if (blockIdx.x == 0 || blockIdx.x == (L_ / RCH) - 1)
        conv_body<true>(x, w, bias, out, sbuf);
    else
        conv_body<false>(x, w, bias, out, sbuf);
}

extern "C" void kernel_launch(void* const* d_in, const int* in_sizes, int n_in,
                              void* d_out, int out_size)
{
    const float* x    = (const float*)d_in[0];   // [B, L, C]
    const float* w    = (const float*)d_in[1];   // [K, C, 1]
    const float* bias = (const float*)d_in[2];   // [C]
    float*       out  = (float*)d_out;           // [B, L, C]

    dim3 grid(L_ / RCH, (C_ / 2) / TPB, B_);     // (256, 2, 8) = 4096 CTAs
    dwconv_kernel<<<grid, TPB>>>(x, w, bias, out);
}